// round 2
// baseline (speedup 1.0000x reference)
#include <cuda_runtime.h>
#include <cstdint>
#include <math.h>

// Problem constants (fixed shapes from reference)
#define SQ   512
#define BA   32
#define HID  1024
#define G4   4096
#define CTAS 128
#define TPB  256

static const size_t SBH = (size_t)SQ * BA * HID; // 16,777,216

// -------- scratch (no cudaMalloc allowed) --------
__device__ float    g_xg[(size_t)SQ * BA * G4];     // 256 MB: precomputed input gates
__device__ float    g_hbuf[2][BA][HID];             // ping-pong h state
__device__ unsigned g_count = 0;
__device__ unsigned g_epoch = 0;

// -------- packed fp32x2 helpers (Blackwell FFMA2) --------
__device__ __forceinline__ unsigned long long ffma2(unsigned long long a,
                                                    unsigned long long b,
                                                    unsigned long long c) {
    unsigned long long d;
    asm("fma.rn.f32x2 %0, %1, %2, %3;" : "=l"(d) : "l"(a), "l"(b), "l"(c));
    return d;
}
__device__ __forceinline__ unsigned long long pk2(float a) {
    unsigned long long r;
    asm("mov.b64 %0, {%1, %1};" : "=l"(r) : "f"(a));
    return r;
}
__device__ __forceinline__ float hsum2(unsigned long long v) {
    float lo, hi;
    asm("mov.b64 {%0, %1}, %2;" : "=f"(lo), "=f"(hi) : "l"(v));
    return lo + hi;
}
__device__ __forceinline__ float sigm(float x) { return 1.0f / (1.0f + expf(-x)); }

// ============================================================================
// Kernel 1: x_gates = X(16384x1024) @ Wih^T(1024x4096) + (bias_ih + bias_hh)
// NT SGEMM, 128x128 block tile, 8x8 thread tile, packed f32x2 over the N dim.
// ============================================================================
__global__ __launch_bounds__(TPB) void gemm_xgates(const float* __restrict__ X,
                                                   const float* __restrict__ W,
                                                   const float* __restrict__ bih,
                                                   const float* __restrict__ bhh) {
    __shared__ unsigned long long As2[16][128]; // a values duplicated into both lanes
    __shared__ float              Bs[16][128];

    const int m0 = blockIdx.y * 128;
    const int n0 = blockIdx.x * 128;
    const int t  = threadIdx.x;
    const int tx = t & 15;   // n-tile (8 cols)
    const int ty = t >> 4;   // m-tile (8 rows)

    unsigned long long acc[8][4];
#pragma unroll
    for (int i = 0; i < 8; ++i)
#pragma unroll
        for (int j = 0; j < 4; ++j) acc[i][j] = 0ULL;

    for (int kt = 0; kt < 1024; kt += 16) {
#pragma unroll
        for (int u = 0; u < 2; ++u) {
            int idx = t + u * 256;
            int r   = idx >> 2;        // 0..127
            int kq  = idx & 3;         // 0..3  (float4 within the 16-wide k tile)
            float4 av = *(const float4*)(X + (size_t)(m0 + r) * 1024 + kt + kq * 4);
            float4 bv = *(const float4*)(W + (size_t)(n0 + r) * 1024 + kt + kq * 4);
            As2[kq * 4 + 0][r] = pk2(av.x);
            As2[kq * 4 + 1][r] = pk2(av.y);
            As2[kq * 4 + 2][r] = pk2(av.z);
            As2[kq * 4 + 3][r] = pk2(av.w);
            Bs[kq * 4 + 0][r] = bv.x;
            Bs[kq * 4 + 1][r] = bv.y;
            Bs[kq * 4 + 2][r] = bv.z;
            Bs[kq * 4 + 3][r] = bv.w;
        }
        __syncthreads();
#pragma unroll
        for (int k = 0; k < 16; ++k) {
            ulonglong2 a01 = *(const ulonglong2*)&As2[k][ty * 8 + 0];
            ulonglong2 a23 = *(const ulonglong2*)&As2[k][ty * 8 + 2];
            ulonglong2 a45 = *(const ulonglong2*)&As2[k][ty * 8 + 4];
            ulonglong2 a67 = *(const ulonglong2*)&As2[k][ty * 8 + 6];
            ulonglong2 b01 = *(const ulonglong2*)&Bs[k][tx * 8 + 0]; // (b0,b1),(b2,b3)
            ulonglong2 b23 = *(const ulonglong2*)&Bs[k][tx * 8 + 4]; // (b4,b5),(b6,b7)
            unsigned long long a[8] = {a01.x, a01.y, a23.x, a23.y, a45.x, a45.y, a67.x, a67.y};
            unsigned long long bb[4] = {b01.x, b01.y, b23.x, b23.y};
#pragma unroll
            for (int i = 0; i < 8; ++i)
#pragma unroll
                for (int j = 0; j < 4; ++j) acc[i][j] = ffma2(a[i], bb[j], acc[i][j]);
        }
        __syncthreads();
    }

    // epilogue: add bias, write to g_xg
    float bias[8];
#pragma unroll
    for (int j = 0; j < 8; ++j) {
        int n = n0 + tx * 8 + j;
        bias[j] = __ldg(bih + n) + __ldg(bhh + n);
    }
#pragma unroll
    for (int i = 0; i < 8; ++i) {
        int m = m0 + ty * 8 + i;
        float ov[8];
#pragma unroll
        for (int j = 0; j < 4; ++j) {
            float lo, hi;
            asm("mov.b64 {%0, %1}, %2;" : "=f"(lo), "=f"(hi) : "l"(acc[i][j]));
            ov[2 * j]     = lo + bias[2 * j];
            ov[2 * j + 1] = hi + bias[2 * j + 1];
        }
        float* op = g_xg + (size_t)m * G4 + n0 + tx * 8;
        *(float4*)(op)     = make_float4(ov[0], ov[1], ov[2], ov[3]);
        *(float4*)(op + 4) = make_float4(ov[4], ov[5], ov[6], ov[7]);
    }
}

// ============================================================================
// Kernel 2: persistent recurrence. 128 CTAs x 256 threads, 1 CTA/SM.
// CTA owns 8 h-columns -> 32 Whh rows (4 gates x 8 cols) resident in smem.
// Per lane: one (batch, col) cell, computes all 4 gate dots (full K=1024),
// keeps c in a register across all 512 steps. Global spin barrier per step.
// ============================================================================
__device__ __forceinline__ void gbar(unsigned tgt) {
    if (threadIdx.x == 0) {
        unsigned prev = atomicAdd(&g_count, 1u);
        if (prev == CTAS - 1u) {
            atomicExch(&g_count, 0u);
            __threadfence();
            atomicAdd(&g_epoch, 1u);
        } else {
            unsigned e;
            do { e = atomicAdd(&g_epoch, 0u); } while ((int)(e - tgt) < 0);
            __threadfence();
        }
    }
    __syncthreads();
}

#define WS_PITCH 1028  // floats; %32==4 -> conflict-free 4-row LDS.128 groups
#define HS_PITCH 132   // floats; %32==4 -> conflict-free 8-batch LDS.128 groups
#define REC_SMEM ((32 * WS_PITCH + 32 * HS_PITCH) * 4)

__global__ __launch_bounds__(TPB, 1) void lstm_rec(const float* __restrict__ Whh,
                                                   float* __restrict__ out) {
    extern __shared__ float sm[];
    float* w_s = sm;                  // [32][WS_PITCH]
    float* h_s = sm + 32 * WS_PITCH;  // [32][HS_PITCH]
    __shared__ unsigned s_base;

    const int t    = threadIdx.x;
    const int cta  = blockIdx.x;
    const int lane = t & 31;
    const int wrp  = t >> 5;
    const int bg   = wrp & 3;   // batch group (4 groups of 8)
    const int cw   = wrp >> 2;  // col group (2 groups of 4)
    const int bi   = lane >> 2; // 0..7
    const int ci   = lane & 3;  // 0..3
    const int b    = bg * 8 + bi;
    const int col  = cw * 4 + ci;       // 0..7 local column
    const int gcol = cta * 8 + col;     // global h column

    if (t == 0) s_base = atomicAdd(&g_epoch, 0u);

    // Load Whh slice: smem row rr -> global row (rr>>3)*HID + cta*8 + (rr&7)
    for (int idx = t; idx < 32 * 256; idx += TPB) {
        int rr = idx >> 8;
        int k4 = idx & 255;
        int grow = (rr >> 3) * HID + cta * 8 + (rr & 7);
        float4 v = *(const float4*)(Whh + (size_t)grow * HID + k4 * 4);
        *(float4*)(w_s + rr * WS_PITCH + k4 * 4) = v;
    }
    // zero h ping buffer 0 (32768 floats == 128 CTAs * 256 threads exactly)
    ((float*)g_hbuf)[cta * TPB + t] = 0.0f;
    __threadfence();
    __syncthreads();

    unsigned tgt = s_base;
    gbar(++tgt); // all weights loaded + h zeroed everywhere

    float c = 0.0f;
    float* hb_base = (float*)g_hbuf;
    const float* w0 = w_s + (0 * 8 + col) * WS_PITCH;
    const float* w1 = w_s + (1 * 8 + col) * WS_PITCH;
    const float* w2 = w_s + (2 * 8 + col) * WS_PITCH;
    const float* w3 = w_s + (3 * 8 + col) * WS_PITCH;

    for (int ts = 0; ts < SQ; ++ts) {
        const float* xp = g_xg + ((size_t)ts * BA + b) * G4 + gcol;
        float xf = __ldg(xp);
        float xi = __ldg(xp + 1024);
        float xg = __ldg(xp + 2048);
        float xo = __ldg(xp + 3072);

        const float* hb = hb_base + (ts & 1) * (BA * HID);
        unsigned long long a0 = 0ULL, a1 = 0ULL, a2 = 0ULL, a3 = 0ULL;

        // software-pipelined staging: prefetch tile kt into regs, store, compute
        const int sbs = (t + 0 * 256) >> 5;  // staging coords per thread (u in 0..3)
        float4 pre[4];
#pragma unroll
        for (int u = 0; u < 4; ++u) {
            int idx = t + u * 256;
            pre[u] = __ldcg((const float4*)(hb + (idx >> 5) * HID + 0 * 128 + (idx & 31) * 4));
        }
        (void)sbs;

        for (int kt = 0; kt < 8; ++kt) {
#pragma unroll
            for (int u = 0; u < 4; ++u) {
                int idx = t + u * 256;
                *(float4*)(h_s + (idx >> 5) * HS_PITCH + (idx & 31) * 4) = pre[u];
            }
            __syncthreads();
            if (kt < 7) {
#pragma unroll
                for (int u = 0; u < 4; ++u) {
                    int idx = t + u * 256;
                    pre[u] = __ldcg((const float4*)(hb + (idx >> 5) * HID + (kt + 1) * 128 + (idx & 31) * 4));
                }
            }
            const float* hr  = h_s + b * HS_PITCH;
            const float* wk0 = w0 + kt * 128;
            const float* wk1 = w1 + kt * 128;
            const float* wk2 = w2 + kt * 128;
            const float* wk3 = w3 + kt * 128;
#pragma unroll 8
            for (int kk = 0; kk < 32; ++kk) {
                ulonglong2 hv = *(const ulonglong2*)(hr + kk * 4);
                ulonglong2 v0 = *(const ulonglong2*)(wk0 + kk * 4);
                ulonglong2 v1 = *(const ulonglong2*)(wk1 + kk * 4);
                ulonglong2 v2 = *(const ulonglong2*)(wk2 + kk * 4);
                ulonglong2 v3 = *(const ulonglong2*)(wk3 + kk * 4);
                a0 = ffma2(hv.x, v0.x, a0); a0 = ffma2(hv.y, v0.y, a0);
                a1 = ffma2(hv.x, v1.x, a1); a1 = ffma2(hv.y, v1.y, a1);
                a2 = ffma2(hv.x, v2.x, a2); a2 = ffma2(hv.y, v2.y, a2);
                a3 = ffma2(hv.x, v3.x, a3); a3 = ffma2(hv.y, v3.y, a3);
            }
            __syncthreads();
        }

        float pf = xf + hsum2(a0);
        float pi = xi + hsum2(a1);
        float pg = xg + hsum2(a2);
        float po = xo + hsum2(a3);
        float fg = sigm(pf);
        float ig = sigm(pi);
        float gg = tanhf(pg);
        float og = sigm(po);
        c = fg * c + ig * gg;
        float hh = og * tanhf(c);

        // publish new h (other parity buffer) + outputs (both identical layers)
        hb_base[((ts + 1) & 1) * (BA * HID) + b * HID + gcol] = hh;
        size_t o1 = ((size_t)ts * BA + b) * HID + gcol;
        out[o1]            = hh;  // h_n layer 0
        out[o1 + SBH]      = hh;  // h_n layer 1 (identical)
        out[o1 + 2 * SBH]  = c;   // c_n layer 0
        out[o1 + 3 * SBH]  = c;   // c_n layer 1

        __threadfence();
        __syncthreads();
        gbar(++tgt);
    }
}

// ============================================================================
extern "C" void kernel_launch(void* const* d_in, const int* in_sizes, int n_in,
                              void* d_out, int out_size) {
    const float* X    = (const float*)d_in[0]; // (512,32,1024)
    const float* Wih  = (const float*)d_in[1]; // (4096,1024)
    const float* Whh  = (const float*)d_in[2]; // (4096,1024)
    const float* bih  = (const float*)d_in[3]; // (4096)
    const float* bhh  = (const float*)d_in[4]; // (4096)
    float*       out  = (float*)d_out;         // h_n(2,512,32,1024) ++ c_n(...)

    cudaFuncSetAttribute(lstm_rec, cudaFuncAttributeMaxDynamicSharedMemorySize, REC_SMEM);

    dim3 g(G4 / 128, (SQ * BA) / 128); // (32, 128)
    gemm_xgates<<<g, TPB>>>(X, Wih, bih, bhh);
    lstm_rec<<<CTAS, TPB, REC_SMEM>>>(Whh, out);
}